// round 3
// baseline (speedup 1.0000x reference)
#include <cuda_runtime.h>
#include <cuda_bf16.h>
#include <cstdint>

// PQLinear: out[b, d*8+j] = sum_k s[b,d,k] * vectors[d,k,j] + bias
//   where s[b,d,k] = sum_{i : indexes[i,d]==k} x[b,i]
//
// Shapes: x[32,4096] f32, vectors[1376,256,8] f32, bias[11008] f32,
//         indexes[4096,1376] int32 (JAX x64 disabled), out[32,11008] f32.

#define IN_DIM   4096
#define OUT_DIM  11008
#define NS       1376
#define KS       256
#define DS       8
#define BATCH    32

#define G        4        // subspaces per block (1376 / 4 = 344 blocks)
#define TILE     256      // i-tile
#define NTILES   (IN_DIM / TILE)
#define NTHREADS 256
#define SPAD     257      // s row pad: bank = (b + k) % 32, conflict-free
#define XPAD     33       // xs row pad

#define S_ELEMS   (G * BATCH * SPAD)   // 32896 floats
#define XS_ELEMS  (TILE * XPAD)        // 8448 floats
#define IDX_ELEMS (G * TILE)           // 1024 ints
#define SMEM_FLOATS (S_ELEMS + 2 * XS_ELEMS + 2 * IDX_ELEMS)
#define SMEM_BYTES  (SMEM_FLOATS * 4)  // 207360 bytes

__device__ __forceinline__ void load_tile(const float* __restrict__ x,
                                          const int* __restrict__ indexes,
                                          float* __restrict__ xs,
                                          int* __restrict__ idxs,
                                          int i0, int d0, int t, int nthr)
{
    // Index tile: each worked i pulls 4 consecutive int32 (16B, aligned since
    // d0 % 4 == 0 and row stride 1376*4 = 5504 is a multiple of 16).
    for (int ti = t; ti < TILE; ti += nthr) {
        int4 a = *(const int4*)(indexes + (size_t)(i0 + ti) * NS + d0);
        idxs[0 * TILE + ti] = a.x;
        idxs[1 * TILE + ti] = a.y;
        idxs[2 * TILE + ti] = a.z;
        idxs[3 * TILE + ti] = a.w;
    }
    // x tile, transposed into xs[ti][b]. Coalesced float4 reads per batch row.
    const int u_cnt = nthr >> 5;          // threads per batch row (8 or 4)
    const int b = t / u_cnt;
    const int u = t % u_cnt;
    const float4* xp = (const float4*)(x + (size_t)b * IN_DIM + i0);
    for (int r = u; r < TILE / 4; r += u_cnt) {
        float4 v = xp[r];
        int ti = r * 4;
        xs[(ti + 0) * XPAD + b] = v.x;
        xs[(ti + 1) * XPAD + b] = v.y;
        xs[(ti + 2) * XPAD + b] = v.z;
        xs[(ti + 3) * XPAD + b] = v.w;
    }
}

__global__ __launch_bounds__(NTHREADS, 1)
void pq_lut_kernel(const float* __restrict__ x,
                   const float* __restrict__ vectors,
                   const float* __restrict__ bias,
                   const int* __restrict__ indexes,
                   float* __restrict__ out)
{
    extern __shared__ float smem[];
    float* s = smem;                               // [G][BATCH][SPAD]
    float* xs0 = smem + S_ELEMS;                   // [TILE][XPAD] buf 0
    float* xs1 = xs0 + XS_ELEMS;                   // buf 1
    int*   id0 = (int*)(xs1 + XS_ELEMS);           // [G][TILE] buf 0
    int*   id1 = id0 + IDX_ELEMS;                  // buf 1

    const int t    = threadIdx.x;
    const int d0   = blockIdx.x * G;
    const int wid  = t >> 5;
    const int lane = t & 31;

    // Zero histogram accumulators.
    for (int i = t; i < S_ELEMS; i += NTHREADS) s[i] = 0.0f;

    // Prime tile 0 (all threads participate).
    load_tile(x, indexes, xs0, id0, 0, d0, t, NTHREADS);
    __syncthreads();

    // Each histogram warp owns one subspace; lane = batch. Exclusive rows ->
    // no atomics, no cross-warp hazards. Same-address LDS/STS ordering within
    // a thread is HW-guaranteed.
    float* srow = s + wid * (BATCH * SPAD) + lane * SPAD;

    for (int tile = 0; tile < NTILES; tile++) {
        const float* xs  = (tile & 1) ? xs1 : xs0;
        const int*   idc = (tile & 1) ? id1 : id0;
        if (wid < G) {
            const int4* kp = (const int4*)(idc + wid * TILE);
            #pragma unroll 4
            for (int q = 0; q < TILE / 4; q++) {
                int4 k4 = kp[q];
                const float* xr = xs + (q * 4) * XPAD + lane;
                float v0 = xr[0 * XPAD];
                float v1 = xr[1 * XPAD];
                float v2 = xr[2 * XPAD];
                float v3 = xr[3 * XPAD];
                srow[k4.x] += v0;
                srow[k4.y] += v1;
                srow[k4.z] += v2;
                srow[k4.w] += v3;
            }
        } else if (tile + 1 < NTILES) {
            // Warps G..7 prefetch the next tile into the other buffer.
            float* nxs = (tile & 1) ? xs0 : xs1;
            int*   nid = (tile & 1) ? id0 : id1;
            load_tile(x, indexes, nxs, nid, (tile + 1) * TILE, d0,
                      t - G * 32, NTHREADS - G * 32);
        }
        __syncthreads();
    }

    // Phase 2: out[b, (d0+g)*8+j] = sum_k s[g][b][k] * v[g][k][j] + bias.
    // Stage the 4 codebooks (4*256*8 floats = 32KB) into the xs region.
    float* vsh = xs0;  // 8192 floats needed, 8448 available in buf 0
    for (int i = t; i < G * KS * DS; i += NTHREADS)
        vsh[i] = vectors[(size_t)d0 * KS * DS + i];
    __syncthreads();

    {
        const int b = t >> 3;     // 32 batches
        const int j = t & 7;      // 8 output dims per subspace
        #pragma unroll
        for (int g = 0; g < G; g++) {
            const float* sg = s + g * (BATCH * SPAD) + b * SPAD;
            const float* vg = vsh + g * (KS * DS) + j;
            float acc = 0.0f;
            #pragma unroll 8
            for (int k = 0; k < KS; k++)
                acc = fmaf(sg[k], vg[k * DS], acc);
            const int n = (d0 + g) * DS + j;
            out[(size_t)b * OUT_DIM + n] = acc + bias[n];
        }
    }
}

extern "C" void kernel_launch(void* const* d_in, const int* in_sizes, int n_in,
                              void* d_out, int out_size)
{
    const float* x       = (const float*)d_in[0];
    const float* vectors = (const float*)d_in[1];
    const float* bias    = (const float*)d_in[2];
    const int*   indexes = (const int*)d_in[3];
    float*       out     = (float*)d_out;

    cudaFuncSetAttribute(pq_lut_kernel,
                         cudaFuncAttributeMaxDynamicSharedMemorySize,
                         SMEM_BYTES);
    pq_lut_kernel<<<NS / G, NTHREADS, SMEM_BYTES>>>(x, vectors, bias, indexes, out);
}

// round 8
// speedup vs baseline: 6.0786x; 6.0786x over previous
#include <cuda_runtime.h>
#include <cuda_fp16.h>
#include <cstdint>

// PQLinear: out[32,11008] = x[32,4096] @ W + bias,
//   W[k, d*8+j] = vectors[d, indexes[k,d], j]
// Fused dequant (fp16) + mma.sync.m16n8k16 with fp32 accumulation.

#define IN_DIM  4096
#define OUT_DIM 11008
#define NS      1376
#define KS      256
#define DS      8
#define BATCH   32

#define NSUB    4                  // subspaces per CTA
#define K_TILE  64
#define K_STEPS (IN_DIM / K_TILE)  // 64
#define NTHR    128
#define NBLK    (NS / NSUB)        // 344

#define A_PAD 72   // halfs/row (144B): 8-row ldmatrix conflict-free
#define B_PAD 40   // halfs/row (80B):  8-row ldmatrix conflict-free

__device__ __align__(16) __half g_vh[NS * KS * DS];
__device__ __align__(16) __half g_xh[BATCH * IN_DIM];

__global__ void convert_kernel(const float* __restrict__ v,
                               const float* __restrict__ x) {
    int i = blockIdx.x * blockDim.x + threadIdx.x;
    if (i < NS * KS * DS) g_vh[i] = __float2half_rn(v[i]);
    if (i < BATCH * IN_DIM) g_xh[i] = __float2half_rn(x[i]);
}

__device__ __forceinline__ void cp16(uint32_t dst, const void* src) {
    asm volatile("cp.async.cg.shared.global [%0], [%1], 16;\n"
                 :: "r"(dst), "l"(src));
}
__device__ __forceinline__ void ldmatrix_x4(uint32_t& a0, uint32_t& a1,
                                            uint32_t& a2, uint32_t& a3,
                                            uint32_t addr) {
    asm volatile("ldmatrix.sync.aligned.m8n8.x4.shared.b16 {%0,%1,%2,%3}, [%4];"
                 : "=r"(a0), "=r"(a1), "=r"(a2), "=r"(a3) : "r"(addr));
}
__device__ __forceinline__ void ldmatrix_x2t(uint32_t& b0, uint32_t& b1,
                                             uint32_t addr) {
    asm volatile("ldmatrix.sync.aligned.m8n8.x2.trans.shared.b16 {%0,%1}, [%2];"
                 : "=r"(b0), "=r"(b1) : "r"(addr));
}
__device__ __forceinline__ void mma16816(float& d0, float& d1, float& d2,
                                         float& d3, uint32_t a0, uint32_t a1,
                                         uint32_t a2, uint32_t a3,
                                         uint32_t b0, uint32_t b1) {
    asm volatile(
        "mma.sync.aligned.m16n8k16.row.col.f32.f16.f16.f32 "
        "{%0,%1,%2,%3}, {%4,%5,%6,%7}, {%8,%9}, {%0,%1,%2,%3};"
        : "+f"(d0), "+f"(d1), "+f"(d2), "+f"(d3)
        : "r"(a0), "r"(a1), "r"(a2), "r"(a3), "r"(b0), "r"(b1));
}

struct Smem {
    __align__(16) __half cb[NSUB * KS * DS];        // 16 KB codebooks
    __align__(16) __half A[2][BATCH * A_PAD];       // 2 x 4.5 KB
    __align__(16) __half B[2][K_TILE * B_PAD];      // 2 x 5 KB
    __align__(16) int    I[2][K_TILE * NSUB];       // 2 x 1 KB
};

__device__ __forceinline__ void load_step(Smem* sm, int s, int buf, int t,
                                          int d0, const int* __restrict__ idxg) {
    // A: 32 rows x 128B (64 fp16) from g_xh -> padded rows. 256 x 16B.
    #pragma unroll
    for (int r = 0; r < 2; r++) {
        int op = t + r * NTHR;
        int row = op >> 3, ch = op & 7;
        uint32_t dst = (uint32_t)__cvta_generic_to_shared(
            &sm->A[buf][row * A_PAD + ch * 8]);
        cp16(dst, g_xh + (size_t)row * IN_DIM + s * K_TILE + ch * 8);
    }
    // idx: 64 k-rows x 4 ints (16B, aligned: d0%4==0, row stride 5504B).
    if (t < K_TILE) {
        uint32_t dst = (uint32_t)__cvta_generic_to_shared(&sm->I[buf][t * 4]);
        cp16(dst, idxg + (size_t)(s * K_TILE + t) * NS + d0);
    }
}

__global__ __launch_bounds__(NTHR)
void pq_mma_kernel(const int* __restrict__ idxg,
                   const float* __restrict__ bias,
                   float* __restrict__ out) {
    __shared__ Smem sm;
    const int t = threadIdx.x;
    const int w = t >> 5, lane = t & 31;
    const int d0 = blockIdx.x * NSUB;
    const int n0 = d0 * DS;

    // Prologue group: codebooks (1024 x 16B) + tiles for step 0.
    {
        const __half* src = g_vh + (size_t)d0 * KS * DS;
        #pragma unroll
        for (int r = 0; r < 8; r++) {
            int c = t + r * NTHR;
            uint32_t dst = (uint32_t)__cvta_generic_to_shared(&sm.cb[c * 8]);
            cp16(dst, src + c * 8);
        }
        load_step(&sm, 0, 0, t, d0, idxg);
        asm volatile("cp.async.commit_group;\n");
    }

    float d[2][4] = {};
    const float4* cb4 = (const float4*)sm.cb;

    for (int s = 0; s < K_STEPS; s++) {
        const int cur = s & 1;
        // (1) All warps done reading buf cur^1 (step s-1 mma/dequant) before
        //     the next cp.asyncs overwrite it.
        __syncthreads();
        if (s + 1 < K_STEPS) {
            load_step(&sm, s + 1, cur ^ 1, t, d0, idxg);
            asm volatile("cp.async.commit_group;\n");
            asm volatile("cp.async.wait_group 1;\n");  // own group-s copies done
        } else {
            asm volatile("cp.async.wait_group 0;\n");
        }
        // (2) wait_group only orders a thread's OWN copies; barrier makes all
        //     threads' group-s data (A/I tiles, prologue cb) visible to all.
        __syncthreads();

        // Dequant step s: 256 codewords -> B[cur]. cw = k*4 + dl.
        #pragma unroll
        for (int r = 0; r < 2; r++) {
            int cw = t + r * NTHR;
            int k = cw >> 2, dl = cw & 3;
            int kidx = sm.I[cur][k * 4 + dl];
            float4 v = cb4[dl * KS + kidx];
            *(float4*)&sm.B[cur][k * B_PAD + dl * DS] = v;
        }
        // (3) B tile visible before ldmatrix.
        __syncthreads();

        // MMA: warp w owns subspace d0+w (8 cols), both 16-row m-tiles.
        uint32_t aB = (uint32_t)__cvta_generic_to_shared(&sm.A[cur][0]);
        uint32_t bB = (uint32_t)__cvta_generic_to_shared(&sm.B[cur][0]);
        #pragma unroll
        for (int kk = 0; kk < 4; kk++) {
            uint32_t b0, b1;
            ldmatrix_x2t(b0, b1,
                bB + ((kk * 16 + (lane & 15)) * B_PAD + w * DS) * 2);
            #pragma unroll
            for (int mt = 0; mt < 2; mt++) {
                uint32_t a0, a1, a2, a3;
                ldmatrix_x4(a0, a1, a2, a3,
                    aB + (mt * 16 + (lane & 15)) * A_PAD * 2 +
                    kk * 32 + (lane >> 4) * 16);
                mma16816(d[mt][0], d[mt][1], d[mt][2], d[mt][3],
                         a0, a1, a2, a3, b0, b1);
            }
        }
    }

    // Epilogue: D frag m16n8 -> out + bias.
    const int cr = lane >> 2, cc = (lane & 3) * 2;
    const int n = n0 + w * DS + cc;
    const float b0v = bias[n], b1v = bias[n + 1];
    #pragma unroll
    for (int mt = 0; mt < 2; mt++) {
        int row = mt * 16 + cr;
        out[(size_t)row * OUT_DIM + n]           = d[mt][0] + b0v;
        out[(size_t)row * OUT_DIM + n + 1]       = d[mt][1] + b1v;
        out[(size_t)(row + 8) * OUT_DIM + n]     = d[mt][2] + b0v;
        out[(size_t)(row + 8) * OUT_DIM + n + 1] = d[mt][3] + b1v;
    }
}

extern "C" void kernel_launch(void* const* d_in, const int* in_sizes, int n_in,
                              void* d_out, int out_size) {
    const float* x       = (const float*)d_in[0];
    const float* vectors = (const float*)d_in[1];
    const float* bias    = (const float*)d_in[2];
    const int*   indexes = (const int*)d_in[3];
    float*       out     = (float*)d_out;

    convert_kernel<<<(NS * KS * DS + 255) / 256, 256>>>(vectors, x);
    pq_mma_kernel<<<NBLK, NTHR>>>(indexes, bias, out);
}